// round 12
// baseline (speedup 1.0000x reference)
#include <cuda_runtime.h>

// PowerFlowUnconstrainedSuperNodeGNN — GB300, round 9
//
// agg[r] = sum_e m_e * (node_in[s_e] @ Wm)  + EF_agg[r] @ Wm_ef + cntf[r]*b
// Node features projected first => per-layer work is a 32-wide CSR gather-sum.
// SpMM uses a 4-edge-per-step vectorized gather: lane=(e4,q), one LDG.128 per
// lane covers 16B of one edge's 128B P-row; 8 unrolled steps per 32-edge tile.

#define NN 100000
#define EE 3200000
#define HD 32
#define NL 3
#define FULL 0xffffffffu

__device__ int    d_cnt[NN];
__device__ int    d_rs[NN + 1];
__device__ int    d_fill[NN];
__device__ int2   d_sm[EE];        // (src, mask bits) in CSR order
__device__ int    d_eid[EE];       // original edge id in CSR order
__device__ float  d_P[(size_t)NN * HD];   // projected node features (per layer)
__device__ float  d_h[(size_t)NN * HD];
__device__ float2 d_V[NN];
__device__ float4 d_EF[NN];
__device__ float  d_cntf[NN];
__device__ float  d_pool[HD];
__device__ float  d_g[HD];

// ---------------------------------------------------------------- zero state
__global__ void k_zero(int n) {
    int i = blockIdx.x * blockDim.x + threadIdx.x;
    if (i < n) d_cnt[i] = 0;
    if (i < HD) { d_pool[i] = 0.f; d_g[i] = 0.f; }
}

// ------------------------------------------- histogram (non-returning REDG)
__global__ void k_hist(const int* __restrict__ rcv, int e) {
    int i = blockIdx.x * blockDim.x + threadIdx.x;
    if (i < e) atomicAdd(&d_cnt[rcv[i]], 1);
}

// --------------------- exclusive scan (1 block); also seeds d_fill = rs
__global__ void k_scan(int n) {
    __shared__ int part[1024];
    int t = threadIdx.x;
    int chunk = (n + 1023) >> 10;
    int lo = t * chunk;
    int hi = min(lo + chunk, n);
    int s = 0;
    for (int i = lo; i < hi; i++) s += d_cnt[i];
    part[t] = s;
    __syncthreads();
    for (int off = 1; off < 1024; off <<= 1) {
        int v = (t >= off) ? part[t - off] : 0;
        __syncthreads();
        part[t] += v;
        __syncthreads();
    }
    int run = (t == 0) ? 0 : part[t - 1];
    for (int i = lo; i < hi; i++) {
        d_rs[i] = run;
        d_fill[i] = run;
        run += d_cnt[i];
    }
    if (t == 1023) d_rs[n] = part[1023];
}

// ------------------------- scatter edges into CSR slots (returning atomic)
__global__ void k_scatter(const int* __restrict__ snd, const int* __restrict__ rcv,
                          const float* __restrict__ mk, int e) {
    int i = blockIdx.x * blockDim.x + threadIdx.x;
    if (i >= e) return;
    int p = atomicAdd(&d_fill[rcv[i]], 1);
    d_sm[p] = make_int2(snd[i], __float_as_int(mk[i]));
    d_eid[p] = i;
}

// ---------------- layer-invariant EF aggregate + masked degree, atomic-free
__global__ void k_ef(const float* __restrict__ ef, int n) {
    int w = (blockIdx.x * blockDim.x + threadIdx.x) >> 5;
    int c = threadIdx.x & 31;
    if (w >= n) return;
    int s0 = d_rs[w], s1 = d_rs[w + 1];
    float ax = 0.f, ay = 0.f, az = 0.f, aw = 0.f, cnt = 0.f;
    for (int e = s0 + c; e < s1; e += 32) {
        float m = __int_as_float(d_sm[e].y);
        int id = __ldg(d_eid + e);
        const float4 f = *reinterpret_cast<const float4*>(ef + (size_t)id * 4);
        ax = fmaf(m, f.x, ax); ay = fmaf(m, f.y, ay);
        az = fmaf(m, f.z, az); aw = fmaf(m, f.w, aw);
        cnt += m;
    }
#pragma unroll
    for (int o = 16; o; o >>= 1) {
        ax += __shfl_xor_sync(FULL, ax, o);
        ay += __shfl_xor_sync(FULL, ay, o);
        az += __shfl_xor_sync(FULL, az, o);
        aw += __shfl_xor_sync(FULL, aw, o);
        cnt += __shfl_xor_sync(FULL, cnt, o);
    }
    if (c == 0) { d_EF[w] = make_float4(ax, ay, az, aw); d_cntf[w] = cnt; }
}

// --------------- init: V=(1,0), h0 = PQ@Win + bin, P0 = [V0,h0]@Wm[0][0:34]
__global__ void k_init(const float* __restrict__ PQ, const float* __restrict__ Win,
                       const float* __restrict__ bin, const float* __restrict__ Wm0,
                       int n) {
    int w = (blockIdx.x * blockDim.x + threadIdx.x) >> 5;
    int c = threadIdx.x & 31;
    if (w >= n) return;
    float p = __ldg(PQ + (size_t)w * 2);
    float q = __ldg(PQ + (size_t)w * 2 + 1);
    float hv = fmaf(p, __ldg(Win + c), fmaf(q, __ldg(Win + HD + c), __ldg(bin + c)));
    float pacc = __ldg(Wm0 + c);                 // V0 = (1, 0): only row 0 counts
#pragma unroll
    for (int k = 0; k < HD; k++)
        pacc = fmaf(__shfl_sync(FULL, hv, k), __ldg(Wm0 + (2 + k) * HD + c), pacc);
    d_P[(size_t)w * HD + c] = pacc;
    if (c == 0) d_V[w] = make_float2(1.f, 0.f);
}

// ---- SpMM + epilogue, 4-edge vectorized gather.
// lane = (e4 = c>>3, q = c&7). Step s: 4 edges; lane loads float4 of edge e4's
// P-row at quad q. Tile = 32 edges = 8 unrolled steps. Padded entries m=0.
__global__ void __launch_bounds__(256) k_spmm(const float* __restrict__ Wt,
                                              const float* __restrict__ bm, int n) {
    __shared__ float bp[HD];
    int tid = threadIdx.x;
    if (tid < HD) bp[tid] = 0.f;
    __syncthreads();
    int w = (blockIdx.x * blockDim.x + tid) >> 5;
    int c = tid & 31;
    if (w < n) {
        int s0 = d_rs[w], s1 = d_rs[w + 1];
        int q  = c & 7;
        int e4 = c >> 3;
        float4 acc = make_float4(0.f, 0.f, 0.f, 0.f);
        for (int base = s0; base < s1; base += 32) {
            int idx = base + c;
            int2 sm = (idx < s1) ? d_sm[idx] : make_int2(0, 0);
#pragma unroll
            for (int s = 0; s < 8; s++) {
                int   src = __shfl_sync(FULL, sm.x, s * 4 + e4);
                float m   = __int_as_float(__shfl_sync(FULL, sm.y, s * 4 + e4));
                const float4 pv = *reinterpret_cast<const float4*>(
                    d_P + (size_t)src * HD + q * 4);
                acc.x = fmaf(m, pv.x, acc.x);
                acc.y = fmaf(m, pv.y, acc.y);
                acc.z = fmaf(m, pv.z, acc.z);
                acc.w = fmaf(m, pv.w, acc.w);
            }
        }
        // reduce the 4 edge-subgroups (lanes differing in bits 3,4 of lane id)
#pragma unroll
        for (int off = 8; off <= 16; off <<= 1) {
            acc.x += __shfl_xor_sync(FULL, acc.x, off);
            acc.y += __shfl_xor_sync(FULL, acc.y, off);
            acc.z += __shfl_xor_sync(FULL, acc.z, off);
            acc.w += __shfl_xor_sync(FULL, acc.w, off);
        }
        if (e4 == 0) {   // lanes 0..7: epilogue for components q*4..q*4+3
            const float4 f = d_EF[w];
            float cf = __ldg(d_cntf + w);
            const float4 w0 = *reinterpret_cast<const float4*>(Wt + 0 * HD + q * 4);
            const float4 w1 = *reinterpret_cast<const float4*>(Wt + 1 * HD + q * 4);
            const float4 w2 = *reinterpret_cast<const float4*>(Wt + 2 * HD + q * 4);
            const float4 w3 = *reinterpret_cast<const float4*>(Wt + 3 * HD + q * 4);
            const float4 bb = *reinterpret_cast<const float4*>(bm + q * 4);
            acc.x = fmaf(f.x, w0.x, fmaf(f.y, w1.x, fmaf(f.z, w2.x, fmaf(f.w, w3.x, fmaf(cf, bb.x, acc.x)))));
            acc.y = fmaf(f.x, w0.y, fmaf(f.y, w1.y, fmaf(f.z, w2.y, fmaf(f.w, w3.y, fmaf(cf, bb.y, acc.y)))));
            acc.z = fmaf(f.x, w0.z, fmaf(f.y, w1.z, fmaf(f.z, w2.z, fmaf(f.w, w3.z, fmaf(cf, bb.z, acc.z)))));
            acc.w = fmaf(f.x, w0.w, fmaf(f.y, w1.w, fmaf(f.z, w2.w, fmaf(f.w, w3.w, fmaf(cf, bb.w, acc.w)))));
            acc.x = fmaxf(acc.x, 0.f);
            acc.y = fmaxf(acc.y, 0.f);
            acc.z = fmaxf(acc.z, 0.f);
            acc.w = fmaxf(acc.w, 0.f);
            *reinterpret_cast<float4*>(d_h + (size_t)w * HD + q * 4) = acc;
            atomicAdd(&bp[q * 4 + 0], acc.x);
            atomicAdd(&bp[q * 4 + 1], acc.y);
            atomicAdd(&bp[q * 4 + 2], acc.z);
            atomicAdd(&bp[q * 4 + 3], acc.w);
        }
    }
    __syncthreads();
    if (tid < HD) atomicAdd(&d_pool[tid], bp[tid]);
}

// -------------------------------- global supernode update (1 block, 32 thr)
__global__ void k_gup(const float* __restrict__ Wg, const float* __restrict__ bg,
                      float inv_n) {
    __shared__ float gin[2 * HD];
    int t = threadIdx.x;
    gin[t] = d_g[t];
    gin[HD + t] = d_pool[t] * inv_n;
    __syncthreads();
    float a = __ldg(bg + t);
#pragma unroll
    for (int k = 0; k < 2 * HD; k++) a = fmaf(gin[k], __ldg(Wg + k * HD + t), a);
    a = fmaxf(a, 0.f);
    d_g[t] = a;
    d_pool[t] = 0.f;   // reset for next layer
}

// --- node update: h'=relu([h,g]@Wn+bn); V+=h'@Wo+bo; P_next=[V',h']@Wm_next
__global__ void k_node(const float* __restrict__ Wn, const float* __restrict__ bn,
                       const float* __restrict__ Wo, const float* __restrict__ bo,
                       const float* __restrict__ Wm_next,
                       float* __restrict__ out, int n) {
    __shared__ float gg[HD];
    if (threadIdx.x < HD) gg[threadIdx.x] = d_g[threadIdx.x];
    __syncthreads();
    int w = (blockIdx.x * blockDim.x + threadIdx.x) >> 5;
    int c = threadIdx.x & 31;
    if (w >= n) return;
    float hv = d_h[(size_t)w * HD + c];          // coalesced; broadcast via shfl
    float a = __ldg(bn + c);
#pragma unroll
    for (int k = 0; k < HD; k++)
        a = fmaf(__shfl_sync(FULL, hv, k), __ldg(Wn + k * HD + c), a);
#pragma unroll
    for (int k = 0; k < HD; k++) a = fmaf(gg[k], __ldg(Wn + (HD + k) * HD + c), a);
    a = fmaxf(a, 0.f);
    float p0 = a * __ldg(Wo + c * 2);
    float p1 = a * __ldg(Wo + c * 2 + 1);
#pragma unroll
    for (int o = 16; o; o >>= 1) {
        p0 += __shfl_xor_sync(FULL, p0, o);
        p1 += __shfl_xor_sync(FULL, p1, o);
    }
    float2 V = d_V[w];
    float v0 = V.x + p0 + __ldg(bo);
    float v1 = V.y + p1 + __ldg(bo + 1);
    if (c == 0) d_V[w] = make_float2(v0, v1);
    if (out) {
        if (c == 0) reinterpret_cast<float2*>(out)[w] = make_float2(v0, v1);
    } else {
        float pacc = fmaf(v0, __ldg(Wm_next + c),
                     fmaf(v1, __ldg(Wm_next + HD + c), 0.f));
#pragma unroll
        for (int k = 0; k < HD; k++)
            pacc = fmaf(__shfl_sync(FULL, a, k), __ldg(Wm_next + (2 + k) * HD + c), pacc);
        d_P[(size_t)w * HD + c] = pacc;
    }
}

extern "C" void kernel_launch(void* const* d_in, const int* in_sizes, int n_in,
                              void* d_out, int out_size) {
    const float* PQ  = (const float*)d_in[0];
    const int*   snd = (const int*)  d_in[1];
    const int*   rcv = (const int*)  d_in[2];
    const float* ef  = (const float*)d_in[3];
    const float* mk  = (const float*)d_in[4];
    const float* Win = (const float*)d_in[5];
    const float* bin = (const float*)d_in[6];
    const float* Wm  = (const float*)d_in[7];   // (L,38,32)
    const float* bm  = (const float*)d_in[8];   // (L,32)
    const float* Wg  = (const float*)d_in[9];   // (L,64,32)
    const float* bg  = (const float*)d_in[10];
    const float* Wn  = (const float*)d_in[11];  // (L,64,32)
    const float* bn  = (const float*)d_in[12];
    const float* Wo  = (const float*)d_in[13];  // (L,32,2)
    const float* bo  = (const float*)d_in[14];  // (L,2)

    int n = in_sizes[0] / 2;
    int e = in_sizes[1];
    if (n > NN) n = NN;
    if (e > EE) e = EE;
    float* out = (float*)d_out;

    int nb_n = (n + 255) / 256;
    int nb_e = (e + 255) / 256;
    int nb_w = (int)(((long long)n * 32 + 255) / 256);

    k_zero<<<nb_n, 256>>>(n);
    k_hist<<<nb_e, 256>>>(rcv, e);
    k_scan<<<1, 1024>>>(n);
    k_scatter<<<nb_e, 256>>>(snd, rcv, mk, e);
    k_ef<<<nb_w, 256>>>(ef, n);
    k_init<<<nb_w, 256>>>(PQ, Win, bin, Wm, n);

    for (int l = 0; l < NL; l++) {
        k_spmm<<<nb_w, 256>>>(Wm + (size_t)l * 38 * HD + 34 * HD,
                              bm + (size_t)l * HD, n);
        k_gup<<<1, 32>>>(Wg + (size_t)l * 64 * HD, bg + (size_t)l * HD,
                         1.0f / (float)n);
        k_node<<<nb_w, 256>>>(Wn + (size_t)l * 64 * HD, bn + (size_t)l * HD,
                              Wo + (size_t)l * HD * 2, bo + (size_t)l * 2,
                              (l < NL - 1) ? (Wm + (size_t)(l + 1) * 38 * HD) : nullptr,
                              (l == NL - 1) ? out : nullptr, n);
    }
}

// round 13
// speedup vs baseline: 1.0497x; 1.0497x over previous
#include <cuda_runtime.h>

// PowerFlowUnconstrainedSuperNodeGNN — GB300, round 13
//
// agg[r] = sum_e m_e * (node_in[s_e] @ Wm)  + EF_agg[r] @ Wm_ef + cntf[r]*b
// Node features projected first => per-layer work is a 32-wide CSR gather-sum.
// SpMM broadcast path: smem-staged metadata tile (no SHFL in inner loop),
// fully unrolled 32-gather body => MLP 32 per warp.

#define NN 100000
#define EE 3200000
#define HD 32
#define NL 3
#define FULL 0xffffffffu

__device__ int    d_cnt[NN];
__device__ int    d_rs[NN + 1];
__device__ int    d_fill[NN];
__device__ int2   d_sm[EE];        // (src, mask bits) in CSR order
__device__ int    d_eid[EE];       // original edge id in CSR order
__device__ float  d_P[(size_t)NN * HD];   // projected node features (per layer)
__device__ float  d_h[(size_t)NN * HD];
__device__ float2 d_V[NN];
__device__ float4 d_EF[NN];
__device__ float  d_cntf[NN];
__device__ float  d_pool[HD];
__device__ float  d_g[HD];

// ---------------------------------------------------------------- zero state
__global__ void k_zero(int n) {
    int i = blockIdx.x * blockDim.x + threadIdx.x;
    if (i < n) d_cnt[i] = 0;
    if (i < HD) { d_pool[i] = 0.f; d_g[i] = 0.f; }
}

// ------------------------------------------- histogram (non-returning REDG)
__global__ void k_hist(const int* __restrict__ rcv, int e) {
    int i = blockIdx.x * blockDim.x + threadIdx.x;
    if (i < e) atomicAdd(&d_cnt[rcv[i]], 1);
}

// --------------------- exclusive scan (1 block); also seeds d_fill = rs
__global__ void k_scan(int n) {
    __shared__ int part[1024];
    int t = threadIdx.x;
    int chunk = (n + 1023) >> 10;
    int lo = t * chunk;
    int hi = min(lo + chunk, n);
    int s = 0;
    for (int i = lo; i < hi; i++) s += d_cnt[i];
    part[t] = s;
    __syncthreads();
    for (int off = 1; off < 1024; off <<= 1) {
        int v = (t >= off) ? part[t - off] : 0;
        __syncthreads();
        part[t] += v;
        __syncthreads();
    }
    int run = (t == 0) ? 0 : part[t - 1];
    for (int i = lo; i < hi; i++) {
        d_rs[i] = run;
        d_fill[i] = run;
        run += d_cnt[i];
    }
    if (t == 1023) d_rs[n] = part[1023];
}

// ------------------------- scatter edges into CSR slots (returning atomic)
__global__ void k_scatter(const int* __restrict__ snd, const int* __restrict__ rcv,
                          const float* __restrict__ mk, int e) {
    int i = blockIdx.x * blockDim.x + threadIdx.x;
    if (i >= e) return;
    int p = atomicAdd(&d_fill[rcv[i]], 1);
    d_sm[p] = make_int2(snd[i], __float_as_int(mk[i]));
    d_eid[p] = i;
}

// ---------------- layer-invariant EF aggregate + masked degree, atomic-free
__global__ void k_ef(const float* __restrict__ ef, int n) {
    int w = (blockIdx.x * blockDim.x + threadIdx.x) >> 5;
    int c = threadIdx.x & 31;
    if (w >= n) return;
    int s0 = d_rs[w], s1 = d_rs[w + 1];
    float ax = 0.f, ay = 0.f, az = 0.f, aw = 0.f, cnt = 0.f;
    for (int e = s0 + c; e < s1; e += 32) {
        float m = __int_as_float(d_sm[e].y);
        int id = __ldg(d_eid + e);
        const float4 f = *reinterpret_cast<const float4*>(ef + (size_t)id * 4);
        ax = fmaf(m, f.x, ax); ay = fmaf(m, f.y, ay);
        az = fmaf(m, f.z, az); aw = fmaf(m, f.w, aw);
        cnt += m;
    }
#pragma unroll
    for (int o = 16; o; o >>= 1) {
        ax += __shfl_xor_sync(FULL, ax, o);
        ay += __shfl_xor_sync(FULL, ay, o);
        az += __shfl_xor_sync(FULL, az, o);
        aw += __shfl_xor_sync(FULL, aw, o);
        cnt += __shfl_xor_sync(FULL, cnt, o);
    }
    if (c == 0) { d_EF[w] = make_float4(ax, ay, az, aw); d_cntf[w] = cnt; }
}

// --------------- init: V=(1,0), h0 = PQ@Win + bin, P0 = [V0,h0]@Wm[0][0:34]
__global__ void k_init(const float* __restrict__ PQ, const float* __restrict__ Win,
                       const float* __restrict__ bin, const float* __restrict__ Wm0,
                       int n) {
    int w = (blockIdx.x * blockDim.x + threadIdx.x) >> 5;
    int c = threadIdx.x & 31;
    if (w >= n) return;
    float p = __ldg(PQ + (size_t)w * 2);
    float q = __ldg(PQ + (size_t)w * 2 + 1);
    float hv = fmaf(p, __ldg(Win + c), fmaf(q, __ldg(Win + HD + c), __ldg(bin + c)));
    float pacc = __ldg(Wm0 + c);                 // V0 = (1, 0): only row 0 counts
#pragma unroll
    for (int k = 0; k < HD; k++)
        pacc = fmaf(__shfl_sync(FULL, hv, k), __ldg(Wm0 + (2 + k) * HD + c), pacc);
    d_P[(size_t)w * HD + c] = pacc;
    if (c == 0) d_V[w] = make_float2(1.f, 0.f);
}

// ---- SpMM + epilogue: h[r]=relu( sum m*P[s] + EF@Wm_ef + cntf*b ); pool.
// Warp per row. Metadata tile staged through smem (no SHFL in inner loop);
// 32 independent gathers in flight per warp. Padded slots: src=0, m=0.
__global__ void __launch_bounds__(256) k_spmm(const float* __restrict__ Wt,
                                              const float* __restrict__ bm, int n) {
    __shared__ float bp[HD];
    __shared__ int2 meta[8][32];
    int tid = threadIdx.x;
    int warp = tid >> 5;
    int c = tid & 31;
    if (tid < HD) bp[tid] = 0.f;
    __syncthreads();
    int w = blockIdx.x * 8 + warp;
    if (w < n) {
        int s0 = d_rs[w], s1 = d_rs[w + 1];
        float acc = 0.f;
        const float* Pc = d_P + c;
        for (int base = s0; base < s1; base += 32) {
            int idx = base + c;
            int2 sm = (idx < s1) ? d_sm[idx] : make_int2(0, 0);
            meta[warp][c] = sm;
            __syncwarp();
#pragma unroll
            for (int j = 0; j < 32; j++) {
                int2 t = meta[warp][j];
                acc = fmaf(__int_as_float(t.y),
                           __ldg(Pc + ((size_t)t.x << 5)), acc);
            }
            __syncwarp();
        }
        const float4 f = d_EF[w];
        acc = fmaf(f.x, __ldg(Wt + c),          acc);
        acc = fmaf(f.y, __ldg(Wt + HD + c),     acc);
        acc = fmaf(f.z, __ldg(Wt + 2 * HD + c), acc);
        acc = fmaf(f.w, __ldg(Wt + 3 * HD + c), acc);
        acc = fmaf(__ldg(d_cntf + w), __ldg(bm + c), acc);
        acc = fmaxf(acc, 0.f);
        d_h[(size_t)w * HD + c] = acc;
        atomicAdd(&bp[c], acc);
    }
    __syncthreads();
    if (tid < HD) atomicAdd(&d_pool[tid], bp[tid]);
}

// -------------------------------- global supernode update (1 block, 32 thr)
__global__ void k_gup(const float* __restrict__ Wg, const float* __restrict__ bg,
                      float inv_n) {
    __shared__ float gin[2 * HD];
    int t = threadIdx.x;
    gin[t] = d_g[t];
    gin[HD + t] = d_pool[t] * inv_n;
    __syncthreads();
    float a = __ldg(bg + t);
#pragma unroll
    for (int k = 0; k < 2 * HD; k++) a = fmaf(gin[k], __ldg(Wg + k * HD + t), a);
    a = fmaxf(a, 0.f);
    d_g[t] = a;
    d_pool[t] = 0.f;   // reset for next layer
}

// --- node update: h'=relu([h,g]@Wn+bn); V+=h'@Wo+bo; P_next=[V',h']@Wm_next
__global__ void k_node(const float* __restrict__ Wn, const float* __restrict__ bn,
                       const float* __restrict__ Wo, const float* __restrict__ bo,
                       const float* __restrict__ Wm_next,
                       float* __restrict__ out, int n) {
    __shared__ float gg[HD];
    if (threadIdx.x < HD) gg[threadIdx.x] = d_g[threadIdx.x];
    __syncthreads();
    int w = (blockIdx.x * blockDim.x + threadIdx.x) >> 5;
    int c = threadIdx.x & 31;
    if (w >= n) return;
    const float* hrow = d_h + (size_t)w * HD;
    float a = __ldg(bn + c);
#pragma unroll
    for (int k = 0; k < HD; k++) a = fmaf(__ldg(hrow + k), __ldg(Wn + k * HD + c), a);
#pragma unroll
    for (int k = 0; k < HD; k++) a = fmaf(gg[k], __ldg(Wn + (HD + k) * HD + c), a);
    a = fmaxf(a, 0.f);
    float p0 = a * __ldg(Wo + c * 2);
    float p1 = a * __ldg(Wo + c * 2 + 1);
#pragma unroll
    for (int o = 16; o; o >>= 1) {
        p0 += __shfl_xor_sync(FULL, p0, o);
        p1 += __shfl_xor_sync(FULL, p1, o);
    }
    float2 V = d_V[w];
    float v0 = V.x + p0 + __ldg(bo);
    float v1 = V.y + p1 + __ldg(bo + 1);
    if (c == 0) d_V[w] = make_float2(v0, v1);
    if (out) {
        if (c == 0) reinterpret_cast<float2*>(out)[w] = make_float2(v0, v1);
    } else {
        float pacc = fmaf(v0, __ldg(Wm_next + c),
                     fmaf(v1, __ldg(Wm_next + HD + c), 0.f));
#pragma unroll
        for (int k = 0; k < HD; k++)
            pacc = fmaf(__shfl_sync(FULL, a, k), __ldg(Wm_next + (2 + k) * HD + c), pacc);
        d_P[(size_t)w * HD + c] = pacc;
    }
}

extern "C" void kernel_launch(void* const* d_in, const int* in_sizes, int n_in,
                              void* d_out, int out_size) {
    const float* PQ  = (const float*)d_in[0];
    const int*   snd = (const int*)  d_in[1];
    const int*   rcv = (const int*)  d_in[2];
    const float* ef  = (const float*)d_in[3];
    const float* mk  = (const float*)d_in[4];
    const float* Win = (const float*)d_in[5];
    const float* bin = (const float*)d_in[6];
    const float* Wm  = (const float*)d_in[7];   // (L,38,32)
    const float* bm  = (const float*)d_in[8];   // (L,32)
    const float* Wg  = (const float*)d_in[9];   // (L,64,32)
    const float* bg  = (const float*)d_in[10];
    const float* Wn  = (const float*)d_in[11];  // (L,64,32)
    const float* bn  = (const float*)d_in[12];
    const float* Wo  = (const float*)d_in[13];  // (L,32,2)
    const float* bo  = (const float*)d_in[14];  // (L,2)

    int n = in_sizes[0] / 2;
    int e = in_sizes[1];
    if (n > NN) n = NN;
    if (e > EE) e = EE;
    float* out = (float*)d_out;

    int nb_n = (n + 255) / 256;
    int nb_e = (e + 255) / 256;
    int nb_w = (int)(((long long)n * 32 + 255) / 256);

    k_zero<<<nb_n, 256>>>(n);
    k_hist<<<nb_e, 256>>>(rcv, e);
    k_scan<<<1, 1024>>>(n);
    k_scatter<<<nb_e, 256>>>(snd, rcv, mk, e);
    k_ef<<<nb_w, 256>>>(ef, n);
    k_init<<<nb_w, 256>>>(PQ, Win, bin, Wm, n);

    for (int l = 0; l < NL; l++) {
        k_spmm<<<nb_w, 256>>>(Wm + (size_t)l * 38 * HD + 34 * HD,
                              bm + (size_t)l * HD, n);
        k_gup<<<1, 32>>>(Wg + (size_t)l * 64 * HD, bg + (size_t)l * HD,
                         1.0f / (float)n);
        k_node<<<nb_w, 256>>>(Wn + (size_t)l * 64 * HD, bn + (size_t)l * HD,
                              Wo + (size_t)l * HD * 2, bo + (size_t)l * 2,
                              (l < NL - 1) ? (Wm + (size_t)(l + 1) * 38 * HD) : nullptr,
                              (l == NL - 1) ? out : nullptr, n);
    }
}